// round 1
// baseline (speedup 1.0000x reference)
#include <cuda_runtime.h>
#include <math.h>

#define BATCH 4
#define SEQ   2048
#define DIM   1024
#define NH    16
#define HD    64
#define MROWS (BATCH*SEQ)   // 8192

// Scratch: 0=xq, 1=xk, 2=xv (head-major [B,H,S,HD]), 3=attn out ([B,S,DIM])
__device__ float g_scratch[4][BATCH*SEQ*DIM];

// ---------------------------------------------------------------------------
// SGEMM: C[M,N] = A[M,K] @ W[K,N], M=8192, N=K=1024.
// 128x128 tile, BK=8, 256 threads, 8x8 per thread.
// HEADMAJOR=1 writes C into head-major layout [B, H, S, HD].
// ---------------------------------------------------------------------------
template<int HEADMAJOR>
__global__ __launch_bounds__(256)
void sgemm_kernel(const float* __restrict__ A_ext, int a_idx,
                  const float* __restrict__ W,
                  float* __restrict__ C_ext, int c_idx)
{
    const int N = DIM, K = DIM;
    const float* A = A_ext ? A_ext : g_scratch[a_idx];
    float*       C = C_ext ? C_ext : g_scratch[c_idx];

    __shared__ float As[8][128];   // As[k][m]
    __shared__ float Bs[8][128];   // Bs[k][n]

    const int tid = threadIdx.x;
    const int m0 = blockIdx.y * 128;
    const int n0 = blockIdx.x * 128;

    // gmem load mapping
    const int arow = tid >> 1;          // 0..127
    const int acol = (tid & 1) * 4;     // 0 or 4
    const int brow = tid >> 5;          // 0..7
    const int bcol = (tid & 31) * 4;    // 0..124

    // compute mapping
    const int ty = tid >> 4, tx = tid & 15;
    const int rb = ty * 8, cb = tx * 8;

    float acc[8][8];
#pragma unroll
    for (int i = 0; i < 8; i++)
#pragma unroll
        for (int j = 0; j < 8; j++) acc[i][j] = 0.0f;

    const float* Aptr = A + (size_t)(m0 + arow) * K + acol;
    const float* Bptr = W + (size_t)brow * N + n0 + bcol;

    for (int k0 = 0; k0 < K; k0 += 8) {
        float4 av = *(const float4*)(Aptr + k0);
        float4 bv = *(const float4*)(Bptr + (size_t)k0 * N);
        __syncthreads();
        As[acol + 0][arow] = av.x;
        As[acol + 1][arow] = av.y;
        As[acol + 2][arow] = av.z;
        As[acol + 3][arow] = av.w;
        *(float4*)&Bs[brow][bcol] = bv;
        __syncthreads();
#pragma unroll
        for (int k = 0; k < 8; k++) {
            float4 a0 = *(const float4*)&As[k][rb];
            float4 a1 = *(const float4*)&As[k][rb + 4];
            float4 b0 = *(const float4*)&Bs[k][cb];
            float4 b1 = *(const float4*)&Bs[k][cb + 4];
            float ar[8] = {a0.x, a0.y, a0.z, a0.w, a1.x, a1.y, a1.z, a1.w};
            float br[8] = {b0.x, b0.y, b0.z, b0.w, b1.x, b1.y, b1.z, b1.w};
#pragma unroll
            for (int i = 0; i < 8; i++)
#pragma unroll
                for (int j = 0; j < 8; j++)
                    acc[i][j] = fmaf(ar[i], br[j], acc[i][j]);
        }
    }

    if (HEADMAJOR) {
        // n block [n0+cb .. n0+cb+7] stays inside one head (8-aligned, HD=64)
        const int h = (n0 + cb) >> 6;
        const int d = (n0 + cb) & 63;
#pragma unroll
        for (int i = 0; i < 8; i++) {
            const int m = m0 + rb + i;
            const int b = m >> 11;       // /SEQ
            const int s = m & 2047;      // %SEQ
            float* crow = C + (((size_t)(b * NH + h) * SEQ + s) * HD + d);
            float4 c0 = {acc[i][0], acc[i][1], acc[i][2], acc[i][3]};
            float4 c1 = {acc[i][4], acc[i][5], acc[i][6], acc[i][7]};
            *(float4*)(crow)     = c0;
            *(float4*)(crow + 4) = c1;
        }
    } else {
#pragma unroll
        for (int i = 0; i < 8; i++) {
            float* crow = C + (size_t)(m0 + rb + i) * N + n0 + cb;
            float4 c0 = {acc[i][0], acc[i][1], acc[i][2], acc[i][3]};
            float4 c1 = {acc[i][4], acc[i][5], acc[i][6], acc[i][7]};
            *(float4*)(crow)     = c0;
            *(float4*)(crow + 4) = c1;
        }
    }
}

// ---------------------------------------------------------------------------
// Flash attention (causal, online softmax).
// Grid: (SEQ/64, BATCH*NH). Block: 256 threads.
// Q tile 64 rows; KV tiles of 64. Each thread owns 4x4 of the 64x64 S tile
// and 4x4 of the 64x64 O tile. Smem = Qt(16K) + KtPs union(16K) + Vs(16K) = 48K.
// ---------------------------------------------------------------------------
__global__ __launch_bounds__(256)
void flash_kernel()
{
    __shared__ float Qt[HD][64];     // Qt[d][r], Q pre-scaled by 1/sqrt(HD)
    __shared__ float KtPs[64][64];   // Kt[d][c] during QK^T, then Ps[c][r] during PV
    __shared__ float Vs[64][HD];     // Vs[c][n]

    const int qt  = blockIdx.x;
    const int bh  = blockIdx.y;
    const int tid = threadIdx.x;
    const int ty = tid >> 4, tx = tid & 15;
    const int rb = ty * 4, cb = tx * 4;
    const int q0 = qt * 64;

    const float* Q  = g_scratch[0] + (size_t)bh * SEQ * HD;
    const float* Kp = g_scratch[1] + (size_t)bh * SEQ * HD;
    const float* Vp = g_scratch[2] + (size_t)bh * SEQ * HD;

    const float sc = 0.125f;   // 1/sqrt(64)
#pragma unroll
    for (int u = 0; u < 4; u++) {
        int lin = tid + u * 256;           // 0..1023 float4s
        int r   = lin >> 4;                // row 0..63
        int dv  = (lin & 15) * 4;          // d 0..60
        float4 qv = *(const float4*)(Q + (size_t)(q0 + r) * HD + dv);
        Qt[dv + 0][r] = qv.x * sc;
        Qt[dv + 1][r] = qv.y * sc;
        Qt[dv + 2][r] = qv.z * sc;
        Qt[dv + 3][r] = qv.w * sc;
    }

    float m_r[4], l_r[4], acc[4][4];
#pragma unroll
    for (int i = 0; i < 4; i++) {
        m_r[i] = -INFINITY;
        l_r[i] = 0.0f;
#pragma unroll
        for (int j = 0; j < 4; j++) acc[i][j] = 0.0f;
    }

    for (int kt = 0; kt <= qt; kt++) {
        const int kv0 = kt * 64;
        __syncthreads();   // prev PV reads done (and Qt ready on first iter)

        // Load K (transposed) and V (direct) tiles
#pragma unroll
        for (int u = 0; u < 4; u++) {
            int lin = tid + u * 256;
            int r   = lin >> 4;
            int dv  = (lin & 15) * 4;
            float4 kv = *(const float4*)(Kp + (size_t)(kv0 + r) * HD + dv);
            KtPs[dv + 0][r] = kv.x;
            KtPs[dv + 1][r] = kv.y;
            KtPs[dv + 2][r] = kv.z;
            KtPs[dv + 3][r] = kv.w;
            float4 vv = *(const float4*)(Vp + (size_t)(kv0 + r) * HD + dv);
            *(float4*)&Vs[r][dv] = vv;
        }
        __syncthreads();

        // S = (Q*sc) @ K^T : 64x64x64
        float s[4][4];
#pragma unroll
        for (int i = 0; i < 4; i++)
#pragma unroll
            for (int j = 0; j < 4; j++) s[i][j] = 0.0f;

#pragma unroll 16
        for (int d = 0; d < HD; d++) {
            float4 qa = *(const float4*)&Qt[d][rb];
            float4 kb = *(const float4*)&KtPs[d][cb];
            float qr[4] = {qa.x, qa.y, qa.z, qa.w};
            float kr[4] = {kb.x, kb.y, kb.z, kb.w};
#pragma unroll
            for (int i = 0; i < 4; i++)
#pragma unroll
                for (int j = 0; j < 4; j++)
                    s[i][j] = fmaf(qr[i], kr[j], s[i][j]);
        }

        if (kt == qt) {
#pragma unroll
            for (int i = 0; i < 4; i++)
#pragma unroll
                for (int j = 0; j < 4; j++)
                    if (cb + j > rb + i) s[i][j] = -INFINITY;
        }

        // Online softmax: 16-lane groups (same ty) own 4 rows redundantly
#pragma unroll
        for (int i = 0; i < 4; i++) {
            float tm = fmaxf(fmaxf(s[i][0], s[i][1]), fmaxf(s[i][2], s[i][3]));
#pragma unroll
            for (int off = 1; off < 16; off <<= 1)
                tm = fmaxf(tm, __shfl_xor_sync(0xffffffffu, tm, off));
            float nm    = fmaxf(m_r[i], tm);
            float scale = __expf(m_r[i] - nm);   // 0 on first tile (m=-inf)
            float rs = 0.0f;
#pragma unroll
            for (int j = 0; j < 4; j++) {
                s[i][j] = __expf(s[i][j] - nm);  // masked -> exp(-inf)=0
                rs += s[i][j];
            }
#pragma unroll
            for (int off = 1; off < 16; off <<= 1)
                rs += __shfl_xor_sync(0xffffffffu, rs, off);
            l_r[i] = l_r[i] * scale + rs;
            m_r[i] = nm;
#pragma unroll
            for (int j = 0; j < 4; j++) acc[i][j] *= scale;
        }

        __syncthreads();   // everyone done reading Kt before overwrite with Ps
#pragma unroll
        for (int j = 0; j < 4; j++) {
            float4 pv = {s[0][j], s[1][j], s[2][j], s[3][j]};
            *(float4*)&KtPs[cb + j][rb] = pv;    // Ps[c][r]
        }
        __syncthreads();

        // O += P @ V : 64x64x64
#pragma unroll 16
        for (int c = 0; c < 64; c++) {
            float4 pa = *(const float4*)&KtPs[c][rb];
            float4 vb = *(const float4*)&Vs[c][cb];
            float pr[4] = {pa.x, pa.y, pa.z, pa.w};
            float vr[4] = {vb.x, vb.y, vb.z, vb.w};
#pragma unroll
            for (int i = 0; i < 4; i++)
#pragma unroll
                for (int j = 0; j < 4; j++)
                    acc[i][j] = fmaf(pr[i], vr[j], acc[i][j]);
        }
    }

    // Epilogue: O / l, write [B, S, DIM] (head h occupies cols h*64..h*64+63)
    const int b = bh >> 4, h = bh & 15;
    float* Oo = g_scratch[3];
#pragma unroll
    for (int i = 0; i < 4; i++) {
        float inv = 1.0f / l_r[i];
        float4 o = {acc[i][0] * inv, acc[i][1] * inv,
                    acc[i][2] * inv, acc[i][3] * inv};
        size_t off = (size_t)(b * SEQ + q0 + rb + i) * DIM + h * HD + cb;
        *(float4*)(Oo + off) = o;
    }
}

// ---------------------------------------------------------------------------
extern "C" void kernel_launch(void* const* d_in, const int* in_sizes, int n_in,
                              void* d_out, int out_size)
{
    const float* q  = (const float*)d_in[0];
    const float* k  = (const float*)d_in[1];
    const float* v  = (const float*)d_in[2];
    const float* wq = (const float*)d_in[3];
    const float* wk = (const float*)d_in[4];
    const float* wv = (const float*)d_in[5];
    const float* wo = (const float*)d_in[6];
    float* out = (float*)d_out;

    dim3 ggrid(DIM / 128, MROWS / 128);   // (8, 64)

    // Projections -> head-major scratch
    sgemm_kernel<1><<<ggrid, 256>>>(q, 0, wq, nullptr, 0);
    sgemm_kernel<1><<<ggrid, 256>>>(k, 0, wk, nullptr, 1);
    sgemm_kernel<1><<<ggrid, 256>>>(v, 0, wv, nullptr, 2);

    // Causal flash attention -> g_scratch[3] as [B,S,DIM]
    flash_kernel<<<dim3(SEQ / 64, BATCH * NH), 256>>>();

    // Output projection -> d_out
    sgemm_kernel<0><<<ggrid, 256>>>(nullptr, 3, wo, out, 0);
}

// round 3
// speedup vs baseline: 1.3823x; 1.3823x over previous
#include <cuda_runtime.h>
#include <math.h>
#include <stdint.h>

#define BATCH 4
#define SEQ   2048
#define DIM   1024
#define NH    16
#define HD    64
#define MROWS (BATCH*SEQ)   // 8192

// Scratch: 0=xq, 1=xk, 2=xv (head-major [B,H,S,HD]), 3=attn out ([B,S,DIM])
__device__ float g_scratch[4][BATCH*SEQ*DIM];

__device__ __forceinline__ uint32_t f2tf32(float x) {
    uint32_t r;
    asm("cvt.rna.tf32.f32 %0, %1;" : "=r"(r) : "f"(x));
    return r;
}

__device__ __forceinline__ void mma_tf32(float c[4],
                                         uint32_t a0, uint32_t a1, uint32_t a2, uint32_t a3,
                                         uint32_t b0, uint32_t b1) {
    asm volatile(
        "mma.sync.aligned.m16n8k8.row.col.f32.tf32.tf32.f32 "
        "{%0,%1,%2,%3}, {%4,%5,%6,%7}, {%8,%9}, {%0,%1,%2,%3};"
        : "+f"(c[0]), "+f"(c[1]), "+f"(c[2]), "+f"(c[3])
        : "r"(a0), "r"(a1), "r"(a2), "r"(a3), "r"(b0), "r"(b1));
}

// ---------------------------------------------------------------------------
// tf32 tensor-core GEMM: C[M,N] = A[M,K] @ W[K,N], M=8192, N=K=1024.
// 128x128 tile, BK=16, 256 threads (8 warps, 4m x 2n), warp tile 32x64.
// Double-buffered smem; rows padded to 136 words => conflict-free LDS frags.
// HEADMAJOR=1 writes C into head-major layout [B, H, S, HD].
// ---------------------------------------------------------------------------
template<int HEADMAJOR>
__global__ __launch_bounds__(256)
void gemm_tf32(const float* __restrict__ A_ext, int a_idx,
               const float* __restrict__ W,
               float* __restrict__ C_ext, int c_idx)
{
    const int N = DIM, K = DIM;
    const float* A = A_ext ? A_ext : g_scratch[a_idx];
    float*       C = C_ext ? C_ext : g_scratch[c_idx];

    __shared__ uint32_t As[2][16][136];   // As[stage][k][m]
    __shared__ uint32_t Bs[2][16][136];   // Bs[stage][k][n]

    const int tid  = threadIdx.x;
    const int warp = tid >> 5, lane = tid & 31;
    const int r4 = lane >> 2, c4 = lane & 3;
    const int wm = (warp >> 1) * 32;     // warp m-offset (0,32,64,96)
    const int wn = (warp & 1) * 64;      // warp n-offset (0,64)
    const int m0 = blockIdx.y * 128;
    const int n0 = blockIdx.x * 128;

    float acc[2][8][4];
#pragma unroll
    for (int mt = 0; mt < 2; mt++)
#pragma unroll
        for (int nt = 0; nt < 8; nt++)
#pragma unroll
            for (int i = 0; i < 4; i++) acc[mt][nt][i] = 0.0f;

    float4 aF[2], bF[2];

    // ---- prologue: load k-tile 0 ----
#pragma unroll
    for (int u = 0; u < 2; u++) {
        int lin = tid + u * 256;
        aF[u] = *(const float4*)(A + (size_t)(m0 + (lin & 127)) * K + ((lin >> 7) << 2));
        bF[u] = *(const float4*)(W + (size_t)(lin >> 5) * N + n0 + ((lin & 31) << 2));
    }
#pragma unroll
    for (int u = 0; u < 2; u++) {
        int lin = tid + u * 256;
        int m = lin & 127, kq = (lin >> 7) << 2;
        As[0][kq + 0][m] = f2tf32(aF[u].x);
        As[0][kq + 1][m] = f2tf32(aF[u].y);
        As[0][kq + 2][m] = f2tf32(aF[u].z);
        As[0][kq + 3][m] = f2tf32(aF[u].w);
        int kb = lin >> 5, nq = (lin & 31) << 2;
        uint4 bv = {f2tf32(bF[u].x), f2tf32(bF[u].y), f2tf32(bF[u].z), f2tf32(bF[u].w)};
        *(uint4*)&Bs[0][kb][nq] = bv;
    }
    __syncthreads();

    int s = 0;
    for (int k0 = 0; k0 < K; k0 += 16) {
        const bool hasNext = (k0 + 16) < K;
        if (hasNext) {
#pragma unroll
            for (int u = 0; u < 2; u++) {
                int lin = tid + u * 256;
                aF[u] = *(const float4*)(A + (size_t)(m0 + (lin & 127)) * K + k0 + 16 + ((lin >> 7) << 2));
                bF[u] = *(const float4*)(W + (size_t)(k0 + 16 + (lin >> 5)) * N + n0 + ((lin & 31) << 2));
            }
        }

        // ---- compute current stage ----
#pragma unroll
        for (int ks = 0; ks < 2; ks++) {
            uint32_t afr[2][4];
#pragma unroll
            for (int mt = 0; mt < 2; mt++) {
                int row = wm + mt * 16 + r4;
                afr[mt][0] = As[s][ks * 8 + c4][row];
                afr[mt][1] = As[s][ks * 8 + c4][row + 8];
                afr[mt][2] = As[s][ks * 8 + c4 + 4][row];
                afr[mt][3] = As[s][ks * 8 + c4 + 4][row + 8];
            }
#pragma unroll
            for (int nt = 0; nt < 8; nt++) {
                int col = wn + nt * 8 + r4;
                uint32_t b0 = Bs[s][ks * 8 + c4][col];
                uint32_t b1 = Bs[s][ks * 8 + c4 + 4][col];
                mma_tf32(acc[0][nt], afr[0][0], afr[0][1], afr[0][2], afr[0][3], b0, b1);
                mma_tf32(acc[1][nt], afr[1][0], afr[1][1], afr[1][2], afr[1][3], b0, b1);
            }
        }

        if (hasNext) {
            int ns = s ^ 1;
#pragma unroll
            for (int u = 0; u < 2; u++) {
                int lin = tid + u * 256;
                int m = lin & 127, kq = (lin >> 7) << 2;
                As[ns][kq + 0][m] = f2tf32(aF[u].x);
                As[ns][kq + 1][m] = f2tf32(aF[u].y);
                As[ns][kq + 2][m] = f2tf32(aF[u].z);
                As[ns][kq + 3][m] = f2tf32(aF[u].w);
                int kb = lin >> 5, nq = (lin & 31) << 2;
                uint4 bv = {f2tf32(bF[u].x), f2tf32(bF[u].y), f2tf32(bF[u].z), f2tf32(bF[u].w)};
                *(uint4*)&Bs[ns][kb][nq] = bv;
            }
        }
        __syncthreads();
        s ^= 1;
    }

    // ---- epilogue ----
#pragma unroll
    for (int mt = 0; mt < 2; mt++) {
#pragma unroll
        for (int nt = 0; nt < 8; nt++) {
            int row = m0 + wm + mt * 16 + r4;
            int col = n0 + wn + nt * 8 + 2 * c4;
            float2 lo = {acc[mt][nt][0], acc[mt][nt][1]};
            float2 hi = {acc[mt][nt][2], acc[mt][nt][3]};
            if (HEADMAJOR) {
                int h = col >> 6, d = col & 63;
                {
                    int b = row >> 11, sq = row & 2047;
                    *(float2*)(C + (((size_t)(b * NH + h) * SEQ + sq) * HD + d)) = lo;
                }
                {
                    int r2 = row + 8;
                    int b = r2 >> 11, sq = r2 & 2047;
                    *(float2*)(C + (((size_t)(b * NH + h) * SEQ + sq) * HD + d)) = hi;
                }
            } else {
                *(float2*)(C + (size_t)row * N + col) = lo;
                *(float2*)(C + (size_t)(row + 8) * N + col) = hi;
            }
        }
    }
}

// ---------------------------------------------------------------------------
// Flash attention (causal, online softmax) — unchanged from R1.
// Grid: (SEQ/64, BATCH*NH). Block: 256 threads.
// ---------------------------------------------------------------------------
__global__ __launch_bounds__(256)
void flash_kernel()
{
    __shared__ float Qt[HD][64];     // Qt[d][r], Q pre-scaled by 1/sqrt(HD)
    __shared__ float KtPs[64][64];   // Kt[d][c] during QK^T, then Ps[c][r] during PV
    __shared__ float Vs[64][HD];     // Vs[c][n]

    const int qt  = blockIdx.x;
    const int bh  = blockIdx.y;
    const int tid = threadIdx.x;
    const int ty = tid >> 4, tx = tid & 15;
    const int rb = ty * 4, cb = tx * 4;
    const int q0 = qt * 64;

    const float* Q  = g_scratch[0] + (size_t)bh * SEQ * HD;
    const float* Kp = g_scratch[1] + (size_t)bh * SEQ * HD;
    const float* Vp = g_scratch[2] + (size_t)bh * SEQ * HD;

    const float sc = 0.125f;   // 1/sqrt(64)
#pragma unroll
    for (int u = 0; u < 4; u++) {
        int lin = tid + u * 256;
        int r   = lin >> 4;
        int dv  = (lin & 15) * 4;
        float4 qv = *(const float4*)(Q + (size_t)(q0 + r) * HD + dv);
        Qt[dv + 0][r] = qv.x * sc;
        Qt[dv + 1][r] = qv.y * sc;
        Qt[dv + 2][r] = qv.z * sc;
        Qt[dv + 3][r] = qv.w * sc;
    }

    float m_r[4], l_r[4], acc[4][4];
#pragma unroll
    for (int i = 0; i < 4; i++) {
        m_r[i] = -INFINITY;
        l_r[i] = 0.0f;
#pragma unroll
        for (int j = 0; j < 4; j++) acc[i][j] = 0.0f;
    }

    for (int kt = 0; kt <= qt; kt++) {
        const int kv0 = kt * 64;
        __syncthreads();

#pragma unroll
        for (int u = 0; u < 4; u++) {
            int lin = tid + u * 256;
            int r   = lin >> 4;
            int dv  = (lin & 15) * 4;
            float4 kv = *(const float4*)(Kp + (size_t)(kv0 + r) * HD + dv);
            KtPs[dv + 0][r] = kv.x;
            KtPs[dv + 1][r] = kv.y;
            KtPs[dv + 2][r] = kv.z;
            KtPs[dv + 3][r] = kv.w;
            float4 vv = *(const float4*)(Vp + (size_t)(kv0 + r) * HD + dv);
            *(float4*)&Vs[r][dv] = vv;
        }
        __syncthreads();

        float s[4][4];
#pragma unroll
        for (int i = 0; i < 4; i++)
#pragma unroll
            for (int j = 0; j < 4; j++) s[i][j] = 0.0f;

#pragma unroll 16
        for (int d = 0; d < HD; d++) {
            float4 qa = *(const float4*)&Qt[d][rb];
            float4 kb = *(const float4*)&KtPs[d][cb];
            float qr[4] = {qa.x, qa.y, qa.z, qa.w};
            float kr[4] = {kb.x, kb.y, kb.z, kb.w};
#pragma unroll
            for (int i = 0; i < 4; i++)
#pragma unroll
                for (int j = 0; j < 4; j++)
                    s[i][j] = fmaf(qr[i], kr[j], s[i][j]);
        }

        if (kt == qt) {
#pragma unroll
            for (int i = 0; i < 4; i++)
#pragma unroll
                for (int j = 0; j < 4; j++)
                    if (cb + j > rb + i) s[i][j] = -INFINITY;
        }

#pragma unroll
        for (int i = 0; i < 4; i++) {
            float tm = fmaxf(fmaxf(s[i][0], s[i][1]), fmaxf(s[i][2], s[i][3]));
#pragma unroll
            for (int off = 1; off < 16; off <<= 1)
                tm = fmaxf(tm, __shfl_xor_sync(0xffffffffu, tm, off));
            float nm    = fmaxf(m_r[i], tm);
            float scale = __expf(m_r[i] - nm);
            float rs = 0.0f;
#pragma unroll
            for (int j = 0; j < 4; j++) {
                s[i][j] = __expf(s[i][j] - nm);
                rs += s[i][j];
            }
#pragma unroll
            for (int off = 1; off < 16; off <<= 1)
                rs += __shfl_xor_sync(0xffffffffu, rs, off);
            l_r[i] = l_r[i] * scale + rs;
            m_r[i] = nm;
#pragma unroll
            for (int j = 0; j < 4; j++) acc[i][j] *= scale;
        }

        __syncthreads();
#pragma unroll
        for (int j = 0; j < 4; j++) {
            float4 pv = {s[0][j], s[1][j], s[2][j], s[3][j]};
            *(float4*)&KtPs[cb + j][rb] = pv;
        }
        __syncthreads();

#pragma unroll 16
        for (int c = 0; c < 64; c++) {
            float4 pa = *(const float4*)&KtPs[c][rb];
            float4 vb = *(const float4*)&Vs[c][cb];
            float pr[4] = {pa.x, pa.y, pa.z, pa.w};
            float vr[4] = {vb.x, vb.y, vb.z, vb.w};
#pragma unroll
            for (int i = 0; i < 4; i++)
#pragma unroll
                for (int j = 0; j < 4; j++)
                    acc[i][j] = fmaf(pr[i], vr[j], acc[i][j]);
        }
    }

    const int b = bh >> 4, h = bh & 15;
    float* Oo = g_scratch[3];
#pragma unroll
    for (int i = 0; i < 4; i++) {
        float inv = 1.0f / l_r[i];
        float4 o = {acc[i][0] * inv, acc[i][1] * inv,
                    acc[i][2] * inv, acc[i][3] * inv};
        size_t off = (size_t)(b * SEQ + q0 + rb + i) * DIM + h * HD + cb;
        *(float4*)(Oo + off) = o;
    }
}

// ---------------------------------------------------------------------------
extern "C" void kernel_launch(void* const* d_in, const int* in_sizes, int n_in,
                              void* d_out, int out_size)
{
    const float* q  = (const float*)d_in[0];
    const float* k  = (const float*)d_in[1];
    const float* v  = (const float*)d_in[2];
    const float* wq = (const float*)d_in[3];
    const float* wk = (const float*)d_in[4];
    const float* wv = (const float*)d_in[5];
    const float* wo = (const float*)d_in[6];
    float* out = (float*)d_out;

    dim3 ggrid(DIM / 128, MROWS / 128);   // (8, 64)

    gemm_tf32<1><<<ggrid, 256>>>(q, 0, wq, nullptr, 0);
    gemm_tf32<1><<<ggrid, 256>>>(k, 0, wk, nullptr, 1);
    gemm_tf32<1><<<ggrid, 256>>>(v, 0, wv, nullptr, 2);

    flash_kernel<<<dim3(SEQ / 64, BATCH * NH), 256>>>();

    gemm_tf32<0><<<ggrid, 256>>>(nullptr, 3, wo, out, 0);
}

// round 4
// speedup vs baseline: 2.4931x; 1.8036x over previous
#include <cuda_runtime.h>
#include <math.h>
#include <stdint.h>

#define BATCH 4
#define SEQ   2048
#define DIM   1024
#define NH    16
#define HD    64
#define MROWS (BATCH*SEQ)   // 8192

// Scratch: 0=xq, 1=xk, 2=xv (head-major [B,H,S,HD]), 3=attn out ([B,S,DIM])
__device__ float g_scratch[4][BATCH*SEQ*DIM];

__device__ __forceinline__ uint32_t f2tf32(float x) {
    uint32_t r;
    asm("cvt.rna.tf32.f32 %0, %1;" : "=r"(r) : "f"(x));
    return r;
}

__device__ __forceinline__ void mma_tf32(float c[4],
                                         uint32_t a0, uint32_t a1, uint32_t a2, uint32_t a3,
                                         uint32_t b0, uint32_t b1) {
    asm volatile(
        "mma.sync.aligned.m16n8k8.row.col.f32.tf32.tf32.f32 "
        "{%0,%1,%2,%3}, {%4,%5,%6,%7}, {%8,%9}, {%0,%1,%2,%3};"
        : "+f"(c[0]), "+f"(c[1]), "+f"(c[2]), "+f"(c[3])
        : "r"(a0), "r"(a1), "r"(a2), "r"(a3), "r"(b0), "r"(b1));
}

// ---------------------------------------------------------------------------
// tf32 tensor-core GEMM: C[M,N] = A[M,K] @ W[K,N]  (unchanged from R3)
// ---------------------------------------------------------------------------
template<int HEADMAJOR>
__global__ __launch_bounds__(256)
void gemm_tf32(const float* __restrict__ A_ext, int a_idx,
               const float* __restrict__ W,
               float* __restrict__ C_ext, int c_idx)
{
    const int N = DIM, K = DIM;
    const float* A = A_ext ? A_ext : g_scratch[a_idx];
    float*       C = C_ext ? C_ext : g_scratch[c_idx];

    __shared__ uint32_t As[2][16][136];
    __shared__ uint32_t Bs[2][16][136];

    const int tid  = threadIdx.x;
    const int warp = tid >> 5, lane = tid & 31;
    const int r4 = lane >> 2, c4 = lane & 3;
    const int wm = (warp >> 1) * 32;
    const int wn = (warp & 1) * 64;
    const int m0 = blockIdx.y * 128;
    const int n0 = blockIdx.x * 128;

    float acc[2][8][4];
#pragma unroll
    for (int mt = 0; mt < 2; mt++)
#pragma unroll
        for (int nt = 0; nt < 8; nt++)
#pragma unroll
            for (int i = 0; i < 4; i++) acc[mt][nt][i] = 0.0f;

    float4 aF[2], bF[2];

#pragma unroll
    for (int u = 0; u < 2; u++) {
        int lin = tid + u * 256;
        aF[u] = *(const float4*)(A + (size_t)(m0 + (lin & 127)) * K + ((lin >> 7) << 2));
        bF[u] = *(const float4*)(W + (size_t)(lin >> 5) * N + n0 + ((lin & 31) << 2));
    }
#pragma unroll
    for (int u = 0; u < 2; u++) {
        int lin = tid + u * 256;
        int m = lin & 127, kq = (lin >> 7) << 2;
        As[0][kq + 0][m] = f2tf32(aF[u].x);
        As[0][kq + 1][m] = f2tf32(aF[u].y);
        As[0][kq + 2][m] = f2tf32(aF[u].z);
        As[0][kq + 3][m] = f2tf32(aF[u].w);
        int kb = lin >> 5, nq = (lin & 31) << 2;
        uint4 bv = {f2tf32(bF[u].x), f2tf32(bF[u].y), f2tf32(bF[u].z), f2tf32(bF[u].w)};
        *(uint4*)&Bs[0][kb][nq] = bv;
    }
    __syncthreads();

    int s = 0;
    for (int k0 = 0; k0 < K; k0 += 16) {
        const bool hasNext = (k0 + 16) < K;
        if (hasNext) {
#pragma unroll
            for (int u = 0; u < 2; u++) {
                int lin = tid + u * 256;
                aF[u] = *(const float4*)(A + (size_t)(m0 + (lin & 127)) * K + k0 + 16 + ((lin >> 7) << 2));
                bF[u] = *(const float4*)(W + (size_t)(k0 + 16 + (lin >> 5)) * N + n0 + ((lin & 31) << 2));
            }
        }

#pragma unroll
        for (int ks = 0; ks < 2; ks++) {
            uint32_t afr[2][4];
#pragma unroll
            for (int mt = 0; mt < 2; mt++) {
                int row = wm + mt * 16 + r4;
                afr[mt][0] = As[s][ks * 8 + c4][row];
                afr[mt][1] = As[s][ks * 8 + c4][row + 8];
                afr[mt][2] = As[s][ks * 8 + c4 + 4][row];
                afr[mt][3] = As[s][ks * 8 + c4 + 4][row + 8];
            }
#pragma unroll
            for (int nt = 0; nt < 8; nt++) {
                int col = wn + nt * 8 + r4;
                uint32_t b0 = Bs[s][ks * 8 + c4][col];
                uint32_t b1 = Bs[s][ks * 8 + c4 + 4][col];
                mma_tf32(acc[0][nt], afr[0][0], afr[0][1], afr[0][2], afr[0][3], b0, b1);
                mma_tf32(acc[1][nt], afr[1][0], afr[1][1], afr[1][2], afr[1][3], b0, b1);
            }
        }

        if (hasNext) {
            int ns = s ^ 1;
#pragma unroll
            for (int u = 0; u < 2; u++) {
                int lin = tid + u * 256;
                int m = lin & 127, kq = (lin >> 7) << 2;
                As[ns][kq + 0][m] = f2tf32(aF[u].x);
                As[ns][kq + 1][m] = f2tf32(aF[u].y);
                As[ns][kq + 2][m] = f2tf32(aF[u].z);
                As[ns][kq + 3][m] = f2tf32(aF[u].w);
                int kb = lin >> 5, nq = (lin & 31) << 2;
                uint4 bv = {f2tf32(bF[u].x), f2tf32(bF[u].y), f2tf32(bF[u].z), f2tf32(bF[u].w)};
                *(uint4*)&Bs[ns][kb][nq] = bv;
            }
        }
        __syncthreads();
        s ^= 1;
    }

#pragma unroll
    for (int mt = 0; mt < 2; mt++) {
#pragma unroll
        for (int nt = 0; nt < 8; nt++) {
            int row = m0 + wm + mt * 16 + r4;
            int col = n0 + wn + nt * 8 + 2 * c4;
            float2 lo = {acc[mt][nt][0], acc[mt][nt][1]};
            float2 hi = {acc[mt][nt][2], acc[mt][nt][3]};
            if (HEADMAJOR) {
                int h = col >> 6, d = col & 63;
                {
                    int b = row >> 11, sq = row & 2047;
                    *(float2*)(C + (((size_t)(b * NH + h) * SEQ + sq) * HD + d)) = lo;
                }
                {
                    int r2 = row + 8;
                    int b = r2 >> 11, sq = r2 & 2047;
                    *(float2*)(C + (((size_t)(b * NH + h) * SEQ + sq) * HD + d)) = hi;
                }
            } else {
                *(float2*)(C + (size_t)row * N + col) = lo;
                *(float2*)(C + (size_t)(row + 8) * N + col) = hi;
            }
        }
    }
}

// ---------------------------------------------------------------------------
// Tensor-core flash attention (causal, online softmax), tf32 mma.
// Grid: (SEQ/64, BATCH*NH). Block: 128 threads (4 warps x 16 Q-rows).
// Smem: Ks[64][76] (union w/ P stride-68 view) + Vs[64][76] = 38 KB.
// ---------------------------------------------------------------------------
__global__ __launch_bounds__(128)
void flash_mma()
{
    __shared__ uint32_t Ks[64 * 76];   // K[n][d], stride 76; reused as P[row][col] stride 68
    __shared__ uint32_t Vs[64 * 76];   // V[c][d], stride 76

    const int qt  = blockIdx.x;
    const int bh  = blockIdx.y;
    const int tid = threadIdx.x;
    const int warp = tid >> 5, lane = tid & 31;
    const int r4 = lane >> 2, c4 = lane & 3;
    const int wr = warp * 16;
    const int q0 = qt * 64;

    const float* Q  = g_scratch[0] + (size_t)bh * SEQ * HD;
    const float* Kp = g_scratch[1] + (size_t)bh * SEQ * HD;
    const float* Vp = g_scratch[2] + (size_t)bh * SEQ * HD;

    // Q A-fragments (tf32, pre-scaled by 1/sqrt(HD)), held in registers
    uint32_t qf[8][4];
    {
        const float sc = 0.125f;
        const float* qr0 = Q + (size_t)(q0 + wr + r4) * HD;
        const float* qr1 = qr0 + 8 * HD;
#pragma unroll
        for (int ks = 0; ks < 8; ks++) {
            int col = ks * 8 + c4;
            qf[ks][0] = f2tf32(qr0[col] * sc);
            qf[ks][1] = f2tf32(qr1[col] * sc);
            qf[ks][2] = f2tf32(qr0[col + 4] * sc);
            qf[ks][3] = f2tf32(qr1[col + 4] * sc);
        }
    }

    float mA = -INFINITY, mB = -INFINITY, lA = 0.0f, lB = 0.0f;
    float o[8][4];
#pragma unroll
    for (int nt = 0; nt < 8; nt++)
#pragma unroll
        for (int i = 0; i < 4; i++) o[nt][i] = 0.0f;

    for (int kt = 0; kt <= qt; kt++) {
        const int kv0 = kt * 64;
        __syncthreads();   // prior PV reads of Ks(P)/Vs complete

        // Load K/V tiles (coalesced float4, convert to tf32)
#pragma unroll
        for (int u = 0; u < 8; u++) {
            int lin = tid + u * 128;
            int r = lin >> 4, dv = (lin & 15) << 2;
            float4 kv = *(const float4*)(Kp + (size_t)(kv0 + r) * HD + dv);
            float4 vv = *(const float4*)(Vp + (size_t)(kv0 + r) * HD + dv);
            uint4 kw = {f2tf32(kv.x), f2tf32(kv.y), f2tf32(kv.z), f2tf32(kv.w)};
            uint4 vw = {f2tf32(vv.x), f2tf32(vv.y), f2tf32(vv.z), f2tf32(vv.w)};
            *(uint4*)&Ks[r * 76 + dv] = kw;
            *(uint4*)&Vs[r * 76 + dv] = vw;
        }
        __syncthreads();

        // S = Q @ K^T  (16x64 per warp)
        float s[8][4];
#pragma unroll
        for (int nt = 0; nt < 8; nt++)
#pragma unroll
            for (int i = 0; i < 4; i++) s[nt][i] = 0.0f;

#pragma unroll
        for (int ks = 0; ks < 8; ks++) {
#pragma unroll
            for (int nt = 0; nt < 8; nt++) {
                uint32_t b0 = Ks[(nt * 8 + r4) * 76 + ks * 8 + c4];
                uint32_t b1 = Ks[(nt * 8 + r4) * 76 + ks * 8 + c4 + 4];
                mma_tf32(s[nt], qf[ks][0], qf[ks][1], qf[ks][2], qf[ks][3], b0, b1);
            }
        }

        // Causal mask on the diagonal tile
        if (kt == qt) {
            const int lrA = wr + r4, lrB = lrA + 8;
#pragma unroll
            for (int nt = 0; nt < 8; nt++) {
                int lc = nt * 8 + 2 * c4;
                if (lc > lrA)     s[nt][0] = -INFINITY;
                if (lc + 1 > lrA) s[nt][1] = -INFINITY;
                if (lc > lrB)     s[nt][2] = -INFINITY;
                if (lc + 1 > lrB) s[nt][3] = -INFINITY;
            }
        }

        // Online softmax on fragments (rows A = wr+r4, B = wr+r4+8)
        float tmA = -INFINITY, tmB = -INFINITY;
#pragma unroll
        for (int nt = 0; nt < 8; nt++) {
            tmA = fmaxf(tmA, fmaxf(s[nt][0], s[nt][1]));
            tmB = fmaxf(tmB, fmaxf(s[nt][2], s[nt][3]));
        }
#pragma unroll
        for (int off = 1; off < 4; off <<= 1) {
            tmA = fmaxf(tmA, __shfl_xor_sync(0xffffffffu, tmA, off));
            tmB = fmaxf(tmB, __shfl_xor_sync(0xffffffffu, tmB, off));
        }
        float nmA = fmaxf(mA, tmA), nmB = fmaxf(mB, tmB);
        float scA = __expf(mA - nmA), scB = __expf(mB - nmB);
        float rsA = 0.0f, rsB = 0.0f;
#pragma unroll
        for (int nt = 0; nt < 8; nt++) {
            s[nt][0] = __expf(s[nt][0] - nmA);
            s[nt][1] = __expf(s[nt][1] - nmA);
            s[nt][2] = __expf(s[nt][2] - nmB);
            s[nt][3] = __expf(s[nt][3] - nmB);
            rsA += s[nt][0] + s[nt][1];
            rsB += s[nt][2] + s[nt][3];
        }
#pragma unroll
        for (int off = 1; off < 4; off <<= 1) {
            rsA += __shfl_xor_sync(0xffffffffu, rsA, off);
            rsB += __shfl_xor_sync(0xffffffffu, rsB, off);
        }
        lA = lA * scA + rsA;  mA = nmA;
        lB = lB * scB + rsB;  mB = nmB;
#pragma unroll
        for (int nt = 0; nt < 8; nt++) {
            o[nt][0] *= scA; o[nt][1] *= scA;
            o[nt][2] *= scB; o[nt][3] *= scB;
        }

        __syncthreads();   // all warps finished reading Ks before overwriting with P

        // Write P (tf32) into the Ks buffer (stride-68 view); rows are warp-private
        uint32_t* P = Ks;
#pragma unroll
        for (int nt = 0; nt < 8; nt++) {
            int colb = nt * 8 + 2 * c4;
            P[(wr + r4) * 68 + colb]         = f2tf32(s[nt][0]);
            P[(wr + r4) * 68 + colb + 1]     = f2tf32(s[nt][1]);
            P[(wr + r4 + 8) * 68 + colb]     = f2tf32(s[nt][2]);
            P[(wr + r4 + 8) * 68 + colb + 1] = f2tf32(s[nt][3]);
        }
        __syncwarp();

        // O += P @ V
#pragma unroll
        for (int ks = 0; ks < 8; ks++) {
            uint32_t a0 = P[(wr + r4) * 68 + ks * 8 + c4];
            uint32_t a1 = P[(wr + r4 + 8) * 68 + ks * 8 + c4];
            uint32_t a2 = P[(wr + r4) * 68 + ks * 8 + c4 + 4];
            uint32_t a3 = P[(wr + r4 + 8) * 68 + ks * 8 + c4 + 4];
#pragma unroll
            for (int nt = 0; nt < 8; nt++) {
                uint32_t b0 = Vs[(ks * 8 + c4) * 76 + nt * 8 + r4];
                uint32_t b1 = Vs[(ks * 8 + c4 + 4) * 76 + nt * 8 + r4];
                mma_tf32(o[nt], a0, a1, a2, a3, b0, b1);
            }
        }
    }

    // Epilogue: O / l -> g_scratch[3] as [B, S, DIM]
    const int b = bh >> 4, h = bh & 15;
    const float invA = 1.0f / lA, invB = 1.0f / lB;
    float* Oo = g_scratch[3];
    const size_t rowA = (size_t)(b * SEQ + q0 + wr + r4) * DIM + h * HD;
    const size_t rowB = rowA + (size_t)8 * DIM;
#pragma unroll
    for (int nt = 0; nt < 8; nt++) {
        int colb = nt * 8 + 2 * c4;
        float2 oA = {o[nt][0] * invA, o[nt][1] * invA};
        float2 oB = {o[nt][2] * invB, o[nt][3] * invB};
        *(float2*)(Oo + rowA + colb) = oA;
        *(float2*)(Oo + rowB + colb) = oB;
    }
}

// ---------------------------------------------------------------------------
extern "C" void kernel_launch(void* const* d_in, const int* in_sizes, int n_in,
                              void* d_out, int out_size)
{
    const float* q  = (const float*)d_in[0];
    const float* k  = (const float*)d_in[1];
    const float* v  = (const float*)d_in[2];
    const float* wq = (const float*)d_in[3];
    const float* wk = (const float*)d_in[4];
    const float* wv = (const float*)d_in[5];
    const float* wo = (const float*)d_in[6];
    float* out = (float*)d_out;

    dim3 ggrid(DIM / 128, MROWS / 128);   // (8, 64)

    gemm_tf32<1><<<ggrid, 256>>>(q, 0, wq, nullptr, 0);
    gemm_tf32<1><<<ggrid, 256>>>(k, 0, wk, nullptr, 1);
    gemm_tf32<1><<<ggrid, 256>>>(v, 0, wv, nullptr, 2);

    flash_mma<<<dim3(SEQ / 64, BATCH * NH), 128>>>();

    gemm_tf32<0><<<ggrid, 256>>>(nullptr, 3, wo, out, 0);
}

// round 5
// speedup vs baseline: 2.9331x; 1.1765x over previous
#include <cuda_runtime.h>
#include <math.h>
#include <stdint.h>

#define BATCH 4
#define SEQ   2048
#define DIM   1024
#define NH    16
#define HD    64
#define MROWS (BATCH*SEQ)   // 8192

// Scratch: 0=xq, 1=xk, 2=xv (head-major [B,H,S,HD]), 3=attn out ([B,S,DIM])
__device__ float g_scratch[4][BATCH*SEQ*DIM];

__device__ __forceinline__ uint32_t f2tf32(float x) {
    uint32_t r;
    asm("cvt.rna.tf32.f32 %0, %1;" : "=r"(r) : "f"(x));
    return r;
}

__device__ __forceinline__ void mma_tf32(float c[4],
                                         uint32_t a0, uint32_t a1, uint32_t a2, uint32_t a3,
                                         uint32_t b0, uint32_t b1) {
    asm volatile(
        "mma.sync.aligned.m16n8k8.row.col.f32.tf32.tf32.f32 "
        "{%0,%1,%2,%3}, {%4,%5,%6,%7}, {%8,%9}, {%0,%1,%2,%3};"
        : "+f"(c[0]), "+f"(c[1]), "+f"(c[2]), "+f"(c[3])
        : "r"(a0), "r"(a1), "r"(a2), "r"(a3), "r"(b0), "r"(b1));
}

#define CP_ASYNC16(dst, src) \
    asm volatile("cp.async.cg.shared.global [%0], [%1], 16;" :: "r"(dst), "l"(src))
#define CP_COMMIT() asm volatile("cp.async.commit_group;")
#define CP_WAIT(n)  asm volatile("cp.async.wait_group %0;" :: "n"(n))

// ---------------------------------------------------------------------------
// tf32 tensor-core GEMM with cp.async 4-stage pipeline.
// C[M,N] = A[M,K] @ W[K,N], M=8192, N=K=1024.
// 128x128 tile, BK=8, 256 threads (8 warps, 4m x 2n), warp tile 32x64.
// Smem (static): A 4x[128][12] fp32 + B 4x[8][136] fp32 = 41984 B.
// A-frag LDS banks (12*r4+c4) distinct; B-frag banks (8*c4+r4) distinct.
// HEADMAJOR=1 writes C into head-major layout [B, H, S, HD].
// ---------------------------------------------------------------------------
#define ASTRIDE 12
#define BSTRIDE 136
#define A_STAGE (128*ASTRIDE)
#define B_STAGE (8*BSTRIDE)
#define NKT     (DIM/8)     // 128 k-tiles

template<int HEADMAJOR>
__global__ __launch_bounds__(256)
void gemm_tf32(const float* __restrict__ A_ext, int a_idx,
               const float* __restrict__ W,
               float* __restrict__ C_ext, int c_idx)
{
    const int N = DIM, K = DIM;
    const float* A = A_ext ? A_ext : g_scratch[a_idx];
    float*       C = C_ext ? C_ext : g_scratch[c_idx];

    __shared__ float Asm[4 * A_STAGE];
    __shared__ float Bsm[4 * B_STAGE];

    const int tid  = threadIdx.x;
    const int warp = tid >> 5, lane = tid & 31;
    const int r4 = lane >> 2, c4 = lane & 3;
    const int wm = (warp >> 1) * 32;
    const int wn = (warp & 1) * 64;
    const int m0 = blockIdx.y * 128;
    const int n0 = blockIdx.x * 128;

    const uint32_t aS = (uint32_t)__cvta_generic_to_shared(Asm);
    const uint32_t bS = (uint32_t)__cvta_generic_to_shared(Bsm);

    // per-thread load coords
    const int arow = tid >> 1, akq = (tid & 1) << 2;      // A: 128 rows x 2 f4
    const int brow = tid >> 5, bnq = (tid & 31) << 2;     // B: 8 rows x 32 f4
    const float* aSrc = A + (size_t)(m0 + arow) * K + akq;
    const float* bSrc = W + (size_t)brow * N + n0 + bnq;
    const uint32_t aDst = aS + (arow * ASTRIDE + akq) * 4;
    const uint32_t bDst = bS + (brow * BSTRIDE + bnq) * 4;

    float acc[2][8][4];
#pragma unroll
    for (int mt = 0; mt < 2; mt++)
#pragma unroll
        for (int nt = 0; nt < 8; nt++)
#pragma unroll
            for (int i = 0; i < 4; i++) acc[mt][nt][i] = 0.0f;

    // prologue: stages 0,1,2
#pragma unroll
    for (int p = 0; p < 3; p++) {
        CP_ASYNC16(aDst + p * A_STAGE * 4, aSrc + p * 8);
        CP_ASYNC16(bDst + p * B_STAGE * 4, bSrc + (size_t)(p * 8) * N);
        CP_COMMIT();
    }

    for (int t = 0; t < NKT; t++) {
        CP_WAIT(2);          // stage t landed
        __syncthreads();     // all threads past compute(t-1); stage t visible

        if (t + 3 < NKT) {
            const int st = (t + 3) & 3;
            CP_ASYNC16(aDst + st * A_STAGE * 4, aSrc + (t + 3) * 8);
            CP_ASYNC16(bDst + st * B_STAGE * 4, bSrc + (size_t)((t + 3) * 8) * N);
            CP_COMMIT();
        }

        const float* As = Asm + (t & 3) * A_STAGE;
        const float* Bs = Bsm + (t & 3) * B_STAGE;

        uint32_t afr[2][4];
#pragma unroll
        for (int mt = 0; mt < 2; mt++) {
            const float* ab = As + (wm + mt * 16 + r4) * ASTRIDE + c4;
            afr[mt][0] = f2tf32(ab[0]);
            afr[mt][1] = f2tf32(ab[8 * ASTRIDE]);
            afr[mt][2] = f2tf32(ab[4]);
            afr[mt][3] = f2tf32(ab[8 * ASTRIDE + 4]);
        }
#pragma unroll
        for (int nt = 0; nt < 8; nt++) {
            const int col = wn + nt * 8 + r4;
            uint32_t b0 = f2tf32(Bs[c4 * BSTRIDE + col]);
            uint32_t b1 = f2tf32(Bs[(c4 + 4) * BSTRIDE + col]);
            mma_tf32(acc[0][nt], afr[0][0], afr[0][1], afr[0][2], afr[0][3], b0, b1);
            mma_tf32(acc[1][nt], afr[1][0], afr[1][1], afr[1][2], afr[1][3], b0, b1);
        }
    }

    // ---- epilogue ----
#pragma unroll
    for (int mt = 0; mt < 2; mt++) {
#pragma unroll
        for (int nt = 0; nt < 8; nt++) {
            int row = m0 + wm + mt * 16 + r4;
            int col = n0 + wn + nt * 8 + 2 * c4;
            float2 lo = {acc[mt][nt][0], acc[mt][nt][1]};
            float2 hi = {acc[mt][nt][2], acc[mt][nt][3]};
            if (HEADMAJOR) {
                int h = col >> 6, d = col & 63;
                {
                    int b = row >> 11, sq = row & 2047;
                    *(float2*)(C + (((size_t)(b * NH + h) * SEQ + sq) * HD + d)) = lo;
                }
                {
                    int r2 = row + 8;
                    int b = r2 >> 11, sq = r2 & 2047;
                    *(float2*)(C + (((size_t)(b * NH + h) * SEQ + sq) * HD + d)) = hi;
                }
            } else {
                *(float2*)(C + (size_t)row * N + col) = lo;
                *(float2*)(C + (size_t)(row + 8) * N + col) = hi;
            }
        }
    }
}

// ---------------------------------------------------------------------------
// Tensor-core flash attention (causal, online softmax), tf32 mma.
// Unchanged from R4.
// ---------------------------------------------------------------------------
__global__ __launch_bounds__(128)
void flash_mma()
{
    __shared__ uint32_t Ks[64 * 76];
    __shared__ uint32_t Vs[64 * 76];

    const int qt  = blockIdx.x;
    const int bh  = blockIdx.y;
    const int tid = threadIdx.x;
    const int warp = tid >> 5, lane = tid & 31;
    const int r4 = lane >> 2, c4 = lane & 3;
    const int wr = warp * 16;
    const int q0 = qt * 64;

    const float* Q  = g_scratch[0] + (size_t)bh * SEQ * HD;
    const float* Kp = g_scratch[1] + (size_t)bh * SEQ * HD;
    const float* Vp = g_scratch[2] + (size_t)bh * SEQ * HD;

    uint32_t qf[8][4];
    {
        const float sc = 0.125f;
        const float* qr0 = Q + (size_t)(q0 + wr + r4) * HD;
        const float* qr1 = qr0 + 8 * HD;
#pragma unroll
        for (int ks = 0; ks < 8; ks++) {
            int col = ks * 8 + c4;
            qf[ks][0] = f2tf32(qr0[col] * sc);
            qf[ks][1] = f2tf32(qr1[col] * sc);
            qf[ks][2] = f2tf32(qr0[col + 4] * sc);
            qf[ks][3] = f2tf32(qr1[col + 4] * sc);
        }
    }

    float mA = -INFINITY, mB = -INFINITY, lA = 0.0f, lB = 0.0f;
    float o[8][4];
#pragma unroll
    for (int nt = 0; nt < 8; nt++)
#pragma unroll
        for (int i = 0; i < 4; i++) o[nt][i] = 0.0f;

    for (int kt = 0; kt <= qt; kt++) {
        const int kv0 = kt * 64;
        __syncthreads();

#pragma unroll
        for (int u = 0; u < 8; u++) {
            int lin = tid + u * 128;
            int r = lin >> 4, dv = (lin & 15) << 2;
            float4 kv = *(const float4*)(Kp + (size_t)(kv0 + r) * HD + dv);
            float4 vv = *(const float4*)(Vp + (size_t)(kv0 + r) * HD + dv);
            uint4 kw = {f2tf32(kv.x), f2tf32(kv.y), f2tf32(kv.z), f2tf32(kv.w)};
            uint4 vw = {f2tf32(vv.x), f2tf32(vv.y), f2tf32(vv.z), f2tf32(vv.w)};
            *(uint4*)&Ks[r * 76 + dv] = kw;
            *(uint4*)&Vs[r * 76 + dv] = vw;
        }
        __syncthreads();

        float s[8][4];
#pragma unroll
        for (int nt = 0; nt < 8; nt++)
#pragma unroll
            for (int i = 0; i < 4; i++) s[nt][i] = 0.0f;

#pragma unroll
        for (int ks = 0; ks < 8; ks++) {
#pragma unroll
            for (int nt = 0; nt < 8; nt++) {
                uint32_t b0 = Ks[(nt * 8 + r4) * 76 + ks * 8 + c4];
                uint32_t b1 = Ks[(nt * 8 + r4) * 76 + ks * 8 + c4 + 4];
                mma_tf32(s[nt], qf[ks][0], qf[ks][1], qf[ks][2], qf[ks][3], b0, b1);
            }
        }

        if (kt == qt) {
            const int lrA = wr + r4, lrB = lrA + 8;
#pragma unroll
            for (int nt = 0; nt < 8; nt++) {
                int lc = nt * 8 + 2 * c4;
                if (lc > lrA)     s[nt][0] = -INFINITY;
                if (lc + 1 > lrA) s[nt][1] = -INFINITY;
                if (lc > lrB)     s[nt][2] = -INFINITY;
                if (lc + 1 > lrB) s[nt][3] = -INFINITY;
            }
        }

        float tmA = -INFINITY, tmB = -INFINITY;
#pragma unroll
        for (int nt = 0; nt < 8; nt++) {
            tmA = fmaxf(tmA, fmaxf(s[nt][0], s[nt][1]));
            tmB = fmaxf(tmB, fmaxf(s[nt][2], s[nt][3]));
        }
#pragma unroll
        for (int off = 1; off < 4; off <<= 1) {
            tmA = fmaxf(tmA, __shfl_xor_sync(0xffffffffu, tmA, off));
            tmB = fmaxf(tmB, __shfl_xor_sync(0xffffffffu, tmB, off));
        }
        float nmA = fmaxf(mA, tmA), nmB = fmaxf(mB, tmB);
        float scA = __expf(mA - nmA), scB = __expf(mB - nmB);
        float rsA = 0.0f, rsB = 0.0f;
#pragma unroll
        for (int nt = 0; nt < 8; nt++) {
            s[nt][0] = __expf(s[nt][0] - nmA);
            s[nt][1] = __expf(s[nt][1] - nmA);
            s[nt][2] = __expf(s[nt][2] - nmB);
            s[nt][3] = __expf(s[nt][3] - nmB);
            rsA += s[nt][0] + s[nt][1];
            rsB += s[nt][2] + s[nt][3];
        }
#pragma unroll
        for (int off = 1; off < 4; off <<= 1) {
            rsA += __shfl_xor_sync(0xffffffffu, rsA, off);
            rsB += __shfl_xor_sync(0xffffffffu, rsB, off);
        }
        lA = lA * scA + rsA;  mA = nmA;
        lB = lB * scB + rsB;  mB = nmB;
#pragma unroll
        for (int nt = 0; nt < 8; nt++) {
            o[nt][0] *= scA; o[nt][1] *= scA;
            o[nt][2] *= scB; o[nt][3] *= scB;
        }

        __syncthreads();

        uint32_t* P = Ks;
#pragma unroll
        for (int nt = 0; nt < 8; nt++) {
            int colb = nt * 8 + 2 * c4;
            P[(wr + r4) * 68 + colb]         = f2tf32(s[nt][0]);
            P[(wr + r4) * 68 + colb + 1]     = f2tf32(s[nt][1]);
            P[(wr + r4 + 8) * 68 + colb]     = f2tf32(s[nt][2]);
            P[(wr + r4 + 8) * 68 + colb + 1] = f2tf32(s[nt][3]);
        }
        __syncwarp();

#pragma unroll
        for (int ks = 0; ks < 8; ks++) {
            uint32_t a0 = P[(wr + r4) * 68 + ks * 8 + c4];
            uint32_t a1 = P[(wr + r4 + 8) * 68 + ks * 8 + c4];
            uint32_t a2 = P[(wr + r4) * 68 + ks * 8 + c4 + 4];
            uint32_t a3 = P[(wr + r4 + 8) * 68 + ks * 8 + c4 + 4];
#pragma unroll
            for (int nt = 0; nt < 8; nt++) {
                uint32_t b0 = Vs[(ks * 8 + c4) * 76 + nt * 8 + r4];
                uint32_t b1 = Vs[(ks * 8 + c4 + 4) * 76 + nt * 8 + r4];
                mma_tf32(o[nt], a0, a1, a2, a3, b0, b1);
            }
        }
    }

    const int b = bh >> 4, h = bh & 15;
    const float invA = 1.0f / lA, invB = 1.0f / lB;
    float* Oo = g_scratch[3];
    const size_t rowA = (size_t)(b * SEQ + q0 + wr + r4) * DIM + h * HD;
    const size_t rowB = rowA + (size_t)8 * DIM;
#pragma unroll
    for (int nt = 0; nt < 8; nt++) {
        int colb = nt * 8 + 2 * c4;
        float2 oA = {o[nt][0] * invA, o[nt][1] * invA};
        float2 oB = {o[nt][2] * invB, o[nt][3] * invB};
        *(float2*)(Oo + rowA + colb) = oA;
        *(float2*)(Oo + rowB + colb) = oB;
    }
}

// ---------------------------------------------------------------------------
extern "C" void kernel_launch(void* const* d_in, const int* in_sizes, int n_in,
                              void* d_out, int out_size)
{
    const float* q  = (const float*)d_in[0];
    const float* k  = (const float*)d_in[1];
    const float* v  = (const float*)d_in[2];
    const float* wq = (const float*)d_in[3];
    const float* wk = (const float*)d_in[4];
    const float* wv = (const float*)d_in[5];
    const float* wo = (const float*)d_in[6];
    float* out = (float*)d_out;

    dim3 ggrid(DIM / 128, MROWS / 128);   // (8, 64)

    gemm_tf32<1><<<ggrid, 256>>>(q, 0, wq, nullptr, 0);
    gemm_tf32<1><<<ggrid, 256>>>(k, 0, wk, nullptr, 1);
    gemm_tf32<1><<<ggrid, 256>>>(v, 0, wv, nullptr, 2);

    flash_mma<<<dim3(SEQ / 64, BATCH * NH), 128>>>();

    gemm_tf32<0><<<ggrid, 256>>>(nullptr, 3, wo, out, 0);
}

// round 7
// speedup vs baseline: 3.0327x; 1.0340x over previous
#include <cuda_runtime.h>
#include <math.h>
#include <stdint.h>

#define BATCH 4
#define SEQ   2048
#define DIM   1024
#define NH    16
#define HD    64
#define MROWS (BATCH*SEQ)   // 8192

// Scratch: 0=xq, 1=xk, 2=xv (head-major [B,H,S,HD]), 3=attn out ([B,S,DIM], tf32-rounded)
__device__ float g_scratch[4][BATCH*SEQ*DIM];
// tf32-rounded activations (q,k,v) and weights
__device__ float g_rnd[3][BATCH*SEQ*DIM];
__device__ float g_wt[4][DIM*DIM];

__device__ __forceinline__ uint32_t f2tf32(float x) {
    uint32_t r;
    asm("cvt.rna.tf32.f32 %0, %1;" : "=r"(r) : "f"(x));
    return r;
}

__device__ __forceinline__ void mma_tf32(float c[4],
                                         uint32_t a0, uint32_t a1, uint32_t a2, uint32_t a3,
                                         uint32_t b0, uint32_t b1) {
    asm volatile(
        "mma.sync.aligned.m16n8k8.row.col.f32.tf32.tf32.f32 "
        "{%0,%1,%2,%3}, {%4,%5,%6,%7}, {%8,%9}, {%0,%1,%2,%3};"
        : "+f"(c[0]), "+f"(c[1]), "+f"(c[2]), "+f"(c[3])
        : "r"(a0), "r"(a1), "r"(a2), "r"(a3), "r"(b0), "r"(b1));
}

#define CP_ASYNC16(dst, src) \
    asm volatile("cp.async.cg.shared.global [%0], [%1], 16;" :: "r"(dst), "l"(src))
#define CP_COMMIT() asm volatile("cp.async.commit_group;")
#define CP_WAIT(n)  asm volatile("cp.async.wait_group %0;" :: "n"(n))

// ---------------------------------------------------------------------------
// Pre-rounding passes (rna tf32), float4 vectorized.
// ---------------------------------------------------------------------------
__global__ __launch_bounds__(256)
void round_acts(const float* __restrict__ q, const float* __restrict__ k,
                const float* __restrict__ v)
{
    const float* src = (blockIdx.y == 0) ? q : (blockIdx.y == 1) ? k : v;
    float* dst = g_rnd[blockIdx.y];
    size_t i = ((size_t)blockIdx.x * 256 + threadIdx.x) * 4;
    float4 x = *(const float4*)(src + i);
    uint4 r = {f2tf32(x.x), f2tf32(x.y), f2tf32(x.z), f2tf32(x.w)};
    *(uint4*)(dst + i) = r;
}

__global__ __launch_bounds__(256)
void round_wts(const float* __restrict__ wq, const float* __restrict__ wk,
               const float* __restrict__ wv, const float* __restrict__ wo)
{
    const float* src = (blockIdx.y == 0) ? wq : (blockIdx.y == 1) ? wk
                      : (blockIdx.y == 2) ? wv : wo;
    float* dst = g_wt[blockIdx.y];
    size_t i = ((size_t)blockIdx.x * 256 + threadIdx.x) * 4;
    float4 x = *(const float4*)(src + i);
    uint4 r = {f2tf32(x.x), f2tf32(x.y), f2tf32(x.z), f2tf32(x.w)};
    *(uint4*)(dst + i) = r;
}

// ---------------------------------------------------------------------------
// tf32 tensor-core GEMM, cp.async 4-stage pipeline, NO conversion in loop
// (all operands pre-rounded). C[M,N] = A[M,K] @ W[K,N], M=8192, N=K=1024.
// 128x128 tile, BK=8, 256 threads (8 warps, 4m x 2n), warp tile 32x64.
// Smem: A 4x[128][12] + B 4x[8][136] u32 = 41984 B.
// A-frag banks (12*r4+c4) distinct; B-frag banks (8*c4+r4) distinct.
// a_idx 0..2 -> g_rnd[a_idx]; a_idx 3 -> g_scratch[3] (rounded by flash).
// ---------------------------------------------------------------------------
#define ASTRIDE 12
#define BSTRIDE 136
#define A_STAGE (128*ASTRIDE)
#define B_STAGE (8*BSTRIDE)
#define NKT     (DIM/8)     // 128 k-tiles

template<int HEADMAJOR>
__global__ __launch_bounds__(256)
void gemm_tf32(int a_idx, int w_idx, float* __restrict__ C_ext, int c_idx)
{
    const int N = DIM, K = DIM;
    const float* A = (a_idx < 3) ? g_rnd[a_idx] : g_scratch[3];
    const float* W = g_wt[w_idx];
    float*       C = C_ext ? C_ext : g_scratch[c_idx];

    __shared__ uint32_t Asm[4 * A_STAGE];
    __shared__ uint32_t Bsm[4 * B_STAGE];

    const int tid  = threadIdx.x;
    const int warp = tid >> 5, lane = tid & 31;
    const int r4 = lane >> 2, c4 = lane & 3;
    const int wm = (warp >> 1) * 32;
    const int wn = (warp & 1) * 64;
    const int m0 = blockIdx.y * 128;
    const int n0 = blockIdx.x * 128;

    const uint32_t aS = (uint32_t)__cvta_generic_to_shared(Asm);
    const uint32_t bS = (uint32_t)__cvta_generic_to_shared(Bsm);

    const int arow = tid >> 1, akq = (tid & 1) << 2;
    const int brow = tid >> 5, bnq = (tid & 31) << 2;
    const float* aSrc = A + (size_t)(m0 + arow) * K + akq;
    const float* bSrc = W + (size_t)brow * N + n0 + bnq;
    const uint32_t aDst = aS + (arow * ASTRIDE + akq) * 4;
    const uint32_t bDst = bS + (brow * BSTRIDE + bnq) * 4;

    float acc[2][8][4];
#pragma unroll
    for (int mt = 0; mt < 2; mt++)
#pragma unroll
        for (int nt = 0; nt < 8; nt++)
#pragma unroll
            for (int i = 0; i < 4; i++) acc[mt][nt][i] = 0.0f;

#pragma unroll
    for (int p = 0; p < 3; p++) {
        CP_ASYNC16(aDst + p * A_STAGE * 4, aSrc + p * 8);
        CP_ASYNC16(bDst + p * B_STAGE * 4, bSrc + (size_t)(p * 8) * N);
        CP_COMMIT();
    }

    for (int t = 0; t < NKT; t++) {
        CP_WAIT(2);
        __syncthreads();

        if (t + 3 < NKT) {
            const int st = (t + 3) & 3;
            CP_ASYNC16(aDst + st * A_STAGE * 4, aSrc + (t + 3) * 8);
            CP_ASYNC16(bDst + st * B_STAGE * 4, bSrc + (size_t)((t + 3) * 8) * N);
            CP_COMMIT();
        }

        const uint32_t* As = Asm + (t & 3) * A_STAGE;
        const uint32_t* Bs = Bsm + (t & 3) * B_STAGE;

        uint32_t afr[2][4];
#pragma unroll
        for (int mt = 0; mt < 2; mt++) {
            const uint32_t* ab = As + (wm + mt * 16 + r4) * ASTRIDE + c4;
            afr[mt][0] = ab[0];
            afr[mt][1] = ab[8 * ASTRIDE];
            afr[mt][2] = ab[4];
            afr[mt][3] = ab[8 * ASTRIDE + 4];
        }
#pragma unroll
        for (int nt = 0; nt < 8; nt++) {
            const int col = wn + nt * 8 + r4;
            uint32_t b0 = Bs[c4 * BSTRIDE + col];
            uint32_t b1 = Bs[(c4 + 4) * BSTRIDE + col];
            mma_tf32(acc[0][nt], afr[0][0], afr[0][1], afr[0][2], afr[0][3], b0, b1);
            mma_tf32(acc[1][nt], afr[1][0], afr[1][1], afr[1][2], afr[1][3], b0, b1);
        }
    }

#pragma unroll
    for (int mt = 0; mt < 2; mt++) {
#pragma unroll
        for (int nt = 0; nt < 8; nt++) {
            int row = m0 + wm + mt * 16 + r4;
            int col = n0 + wn + nt * 8 + 2 * c4;
            float2 lo = {acc[mt][nt][0], acc[mt][nt][1]};
            float2 hi = {acc[mt][nt][2], acc[mt][nt][3]};
            if (HEADMAJOR) {
                int h = col >> 6, d = col & 63;
                {
                    int b = row >> 11, sq = row & 2047;
                    *(float2*)(C + (((size_t)(b * NH + h) * SEQ + sq) * HD + d)) = lo;
                }
                {
                    int r2 = row + 8;
                    int b = r2 >> 11, sq = r2 & 2047;
                    *(float2*)(C + (((size_t)(b * NH + h) * SEQ + sq) * HD + d)) = hi;
                }
            } else {
                *(float2*)(C + (size_t)row * N + col) = lo;
                *(float2*)(C + (size_t)(row + 8) * N + col) = hi;
            }
        }
    }
}

// ---------------------------------------------------------------------------
// Tensor-core flash attention (tf32 mma.sync), longest-first schedule.
// Epilogue stores tf32-rounded output (feeds the final GEMM pre-rounded).
// ---------------------------------------------------------------------------
__global__ __launch_bounds__(128)
void flash_mma()
{
    __shared__ uint32_t Ks[64 * 76];
    __shared__ uint32_t Vs[64 * 76];

    const int qt  = gridDim.x - 1 - blockIdx.x;
    const int bh  = blockIdx.y;
    const int tid = threadIdx.x;
    const int warp = tid >> 5, lane = tid & 31;
    const int r4 = lane >> 2, c4 = lane & 3;
    const int wr = warp * 16;
    const int q0 = qt * 64;

    const float* Q  = g_scratch[0] + (size_t)bh * SEQ * HD;
    const float* Kp = g_scratch[1] + (size_t)bh * SEQ * HD;
    const float* Vp = g_scratch[2] + (size_t)bh * SEQ * HD;

    uint32_t qf[8][4];
    {
        const float sc = 0.125f;
        const float* qr0 = Q + (size_t)(q0 + wr + r4) * HD;
        const float* qr1 = qr0 + 8 * HD;
#pragma unroll
        for (int ks = 0; ks < 8; ks++) {
            int col = ks * 8 + c4;
            qf[ks][0] = f2tf32(qr0[col] * sc);
            qf[ks][1] = f2tf32(qr1[col] * sc);
            qf[ks][2] = f2tf32(qr0[col + 4] * sc);
            qf[ks][3] = f2tf32(qr1[col + 4] * sc);
        }
    }

    float mA = -INFINITY, mB = -INFINITY, lA = 0.0f, lB = 0.0f;
    float o[8][4];
#pragma unroll
    for (int nt = 0; nt < 8; nt++)
#pragma unroll
        for (int i = 0; i < 4; i++) o[nt][i] = 0.0f;

    for (int kt = 0; kt <= qt; kt++) {
        const int kv0 = kt * 64;
        __syncthreads();

#pragma unroll
        for (int u = 0; u < 8; u++) {
            int lin = tid + u * 128;
            int r = lin >> 4, dv = (lin & 15) << 2;
            float4 kv = *(const float4*)(Kp + (size_t)(kv0 + r) * HD + dv);
            float4 vv = *(const float4*)(Vp + (size_t)(kv0 + r) * HD + dv);
            uint4 kw = {f2tf32(kv.x), f2tf32(kv.y), f2tf32(kv.z), f2tf32(kv.w)};
            uint4 vw = {f2tf32(vv.x), f2tf32(vv.y), f2tf32(vv.z), f2tf32(vv.w)};
            *(uint4*)&Ks[r * 76 + dv] = kw;
            *(uint4*)&Vs[r * 76 + dv] = vw;
        }
        __syncthreads();

        float s[8][4];
#pragma unroll
        for (int nt = 0; nt < 8; nt++)
#pragma unroll
            for (int i = 0; i < 4; i++) s[nt][i] = 0.0f;

#pragma unroll
        for (int ks = 0; ks < 8; ks++) {
#pragma unroll
            for (int nt = 0; nt < 8; nt++) {
                uint32_t b0 = Ks[(nt * 8 + r4) * 76 + ks * 8 + c4];
                uint32_t b1 = Ks[(nt * 8 + r4) * 76 + ks * 8 + c4 + 4];
                mma_tf32(s[nt], qf[ks][0], qf[ks][1], qf[ks][2], qf[ks][3], b0, b1);
            }
        }

        if (kt == qt) {
            const int lrA = wr + r4, lrB = lrA + 8;
#pragma unroll
            for (int nt = 0; nt < 8; nt++) {
                int lc = nt * 8 + 2 * c4;
                if (lc > lrA)     s[nt][0] = -INFINITY;
                if (lc + 1 > lrA) s[nt][1] = -INFINITY;
                if (lc > lrB)     s[nt][2] = -INFINITY;
                if (lc + 1 > lrB) s[nt][3] = -INFINITY;
            }
        }

        float tmA = -INFINITY, tmB = -INFINITY;
#pragma unroll
        for (int nt = 0; nt < 8; nt++) {
            tmA = fmaxf(tmA, fmaxf(s[nt][0], s[nt][1]));
            tmB = fmaxf(tmB, fmaxf(s[nt][2], s[nt][3]));
        }
#pragma unroll
        for (int off = 1; off < 4; off <<= 1) {
            tmA = fmaxf(tmA, __shfl_xor_sync(0xffffffffu, tmA, off));
            tmB = fmaxf(tmB, __shfl_xor_sync(0xffffffffu, tmB, off));
        }
        float nmA = fmaxf(mA, tmA), nmB = fmaxf(mB, tmB);
        float scA = __expf(mA - nmA), scB = __expf(mB - nmB);
        float rsA = 0.0f, rsB = 0.0f;
#pragma unroll
        for (int nt = 0; nt < 8; nt++) {
            s[nt][0] = __expf(s[nt][0] - nmA);
            s[nt][1] = __expf(s[nt][1] - nmA);
            s[nt][2] = __expf(s[nt][2] - nmB);
            s[nt][3] = __expf(s[nt][3] - nmB);
            rsA += s[nt][0] + s[nt][1];
            rsB += s[nt][2] + s[nt][3];
        }
#pragma unroll
        for (int off = 1; off < 4; off <<= 1) {
            rsA += __shfl_xor_sync(0xffffffffu, rsA, off);
            rsB += __shfl_xor_sync(0xffffffffu, rsB, off);
        }
        lA = lA * scA + rsA;  mA = nmA;
        lB = lB * scB + rsB;  mB = nmB;
#pragma unroll
        for (int nt = 0; nt < 8; nt++) {
            o[nt][0] *= scA; o[nt][1] *= scA;
            o[nt][2] *= scB; o[nt][3] *= scB;
        }

        __syncthreads();

        uint32_t* P = Ks;
#pragma unroll
        for (int nt = 0; nt < 8; nt++) {
            int colb = nt * 8 + 2 * c4;
            P[(wr + r4) * 68 + colb]         = f2tf32(s[nt][0]);
            P[(wr + r4) * 68 + colb + 1]     = f2tf32(s[nt][1]);
            P[(wr + r4 + 8) * 68 + colb]     = f2tf32(s[nt][2]);
            P[(wr + r4 + 8) * 68 + colb + 1] = f2tf32(s[nt][3]);
        }
        __syncwarp();

#pragma unroll
        for (int ks = 0; ks < 8; ks++) {
            uint32_t a0 = P[(wr + r4) * 68 + ks * 8 + c4];
            uint32_t a1 = P[(wr + r4 + 8) * 68 + ks * 8 + c4];
            uint32_t a2 = P[(wr + r4) * 68 + ks * 8 + c4 + 4];
            uint32_t a3 = P[(wr + r4 + 8) * 68 + ks * 8 + c4 + 4];
#pragma unroll
            for (int nt = 0; nt < 8; nt++) {
                uint32_t b0 = Vs[(ks * 8 + c4) * 76 + nt * 8 + r4];
                uint32_t b1 = Vs[(ks * 8 + c4 + 4) * 76 + nt * 8 + r4];
                mma_tf32(o[nt], a0, a1, a2, a3, b0, b1);
            }
        }
    }

    // Epilogue: O / l, tf32-rounded, -> g_scratch[3] as [B, S, DIM]
    const int b = bh >> 4, h = bh & 15;
    const float invA = 1.0f / lA, invB = 1.0f / lB;
    float* Oo = g_scratch[3];
    const size_t rowA = (size_t)(b * SEQ + q0 + wr + r4) * DIM + h * HD;
    const size_t rowB = rowA + (size_t)8 * DIM;
#pragma unroll
    for (int nt = 0; nt < 8; nt++) {
        int colb = nt * 8 + 2 * c4;
        uint2 oA = {f2tf32(o[nt][0] * invA), f2tf32(o[nt][1] * invA)};
        uint2 oB = {f2tf32(o[nt][2] * invB), f2tf32(o[nt][3] * invB)};
        *(uint2*)(Oo + rowA + colb) = oA;
        *(uint2*)(Oo + rowB + colb) = oB;
    }
}

// ---------------------------------------------------------------------------
extern "C" void kernel_launch(void* const* d_in, const int* in_sizes, int n_in,
                              void* d_out, int out_size)
{
    const float* q  = (const float*)d_in[0];
    const float* k  = (const float*)d_in[1];
    const float* v  = (const float*)d_in[2];
    const float* wq = (const float*)d_in[3];
    const float* wk = (const float*)d_in[4];
    const float* wv = (const float*)d_in[5];
    const float* wo = (const float*)d_in[6];
    float* out = (float*)d_out;

    // Pre-round activations and weights to tf32 (rna)
    round_acts<<<dim3(MROWS * DIM / 1024, 3), 256>>>(q, k, v);
    round_wts<<<dim3(DIM * DIM / 1024, 4), 256>>>(wq, wk, wv, wo);

    dim3 ggrid(DIM / 128, MROWS / 128);   // (8, 64)

    gemm_tf32<1><<<ggrid, 256>>>(0, 0, nullptr, 0);
    gemm_tf32<1><<<ggrid, 256>>>(1, 1, nullptr, 1);
    gemm_tf32<1><<<ggrid, 256>>>(2, 2, nullptr, 2);

    flash_mma<<<dim3(SEQ / 64, BATCH * NH), 128>>>();

    gemm_tf32<0><<<ggrid, 256>>>(3, 3, out, 0);
}

// round 8
// speedup vs baseline: 3.0560x; 1.0077x over previous
#include <cuda_runtime.h>
#include <math.h>
#include <stdint.h>

#define BATCH 4
#define SEQ   2048
#define DIM   1024
#define NH    16
#define HD    64
#define MROWS (BATCH*SEQ)   // 8192

// Scratch: 0=xq (pre-scaled+tf32), 1=xk (tf32), 2=xv (tf32)  head-major [B,H,S,HD]
//          3=attn out ([B,S,DIM], tf32-rounded)
__device__ float g_scratch[4][BATCH*SEQ*DIM];
// tf32-rounded activations (q,k,v inputs) and weights
__device__ float g_rnd[3][BATCH*SEQ*DIM];
__device__ float g_wt[4][DIM*DIM];

__device__ __forceinline__ uint32_t f2tf32(float x) {
    uint32_t r;
    asm("cvt.rna.tf32.f32 %0, %1;" : "=r"(r) : "f"(x));
    return r;
}

__device__ __forceinline__ void mma_tf32(float c[4],
                                         uint32_t a0, uint32_t a1, uint32_t a2, uint32_t a3,
                                         uint32_t b0, uint32_t b1) {
    asm volatile(
        "mma.sync.aligned.m16n8k8.row.col.f32.tf32.tf32.f32 "
        "{%0,%1,%2,%3}, {%4,%5,%6,%7}, {%8,%9}, {%0,%1,%2,%3};"
        : "+f"(c[0]), "+f"(c[1]), "+f"(c[2]), "+f"(c[3])
        : "r"(a0), "r"(a1), "r"(a2), "r"(a3), "r"(b0), "r"(b1));
}

#define CP_ASYNC16(dst, src) \
    asm volatile("cp.async.cg.shared.global [%0], [%1], 16;" :: "r"(dst), "l"(src))
#define CP_COMMIT() asm volatile("cp.async.commit_group;")
#define CP_WAIT(n)  asm volatile("cp.async.wait_group %0;" :: "n"(n))

// ---------------------------------------------------------------------------
// Pre-rounding passes (rna tf32), float4 vectorized.
// ---------------------------------------------------------------------------
__global__ __launch_bounds__(256)
void round_acts(const float* __restrict__ q, const float* __restrict__ k,
                const float* __restrict__ v)
{
    const float* src = (blockIdx.y == 0) ? q : (blockIdx.y == 1) ? k : v;
    float* dst = g_rnd[blockIdx.y];
    size_t i = ((size_t)blockIdx.x * 256 + threadIdx.x) * 4;
    float4 x = *(const float4*)(src + i);
    uint4 r = {f2tf32(x.x), f2tf32(x.y), f2tf32(x.z), f2tf32(x.w)};
    *(uint4*)(dst + i) = r;
}

__global__ __launch_bounds__(256)
void round_wts(const float* __restrict__ wq, const float* __restrict__ wk,
               const float* __restrict__ wv, const float* __restrict__ wo)
{
    const float* src = (blockIdx.y == 0) ? wq : (blockIdx.y == 1) ? wk
                      : (blockIdx.y == 2) ? wv : wo;
    float* dst = g_wt[blockIdx.y];
    size_t i = ((size_t)blockIdx.x * 256 + threadIdx.x) * 4;
    float4 x = *(const float4*)(src + i);
    uint4 r = {f2tf32(x.x), f2tf32(x.y), f2tf32(x.z), f2tf32(x.w)};
    *(uint4*)(dst + i) = r;
}

// ---------------------------------------------------------------------------
// tf32 tensor-core GEMM, cp.async 4-stage pipeline (R7 core).
// ROUND=1: epilogue stores round_tf32(val * oscale)  (Q gets oscale=0.125).
// ---------------------------------------------------------------------------
#define ASTRIDE 12
#define BSTRIDE 136
#define A_STAGE (128*ASTRIDE)
#define B_STAGE (8*BSTRIDE)
#define NKT     (DIM/8)     // 128 k-tiles

template<int HEADMAJOR, int ROUND>
__global__ __launch_bounds__(256)
void gemm_tf32(int a_idx, int w_idx, float* __restrict__ C_ext, int c_idx,
               float oscale)
{
    const int N = DIM, K = DIM;
    const float* A = (a_idx < 3) ? g_rnd[a_idx] : g_scratch[3];
    const float* W = g_wt[w_idx];
    float*       C = C_ext ? C_ext : g_scratch[c_idx];

    __shared__ uint32_t Asm[4 * A_STAGE];
    __shared__ uint32_t Bsm[4 * B_STAGE];

    const int tid  = threadIdx.x;
    const int warp = tid >> 5, lane = tid & 31;
    const int r4 = lane >> 2, c4 = lane & 3;
    const int wm = (warp >> 1) * 32;
    const int wn = (warp & 1) * 64;
    const int m0 = blockIdx.y * 128;
    const int n0 = blockIdx.x * 128;

    const uint32_t aS = (uint32_t)__cvta_generic_to_shared(Asm);
    const uint32_t bS = (uint32_t)__cvta_generic_to_shared(Bsm);

    const int arow = tid >> 1, akq = (tid & 1) << 2;
    const int brow = tid >> 5, bnq = (tid & 31) << 2;
    const float* aSrc = A + (size_t)(m0 + arow) * K + akq;
    const float* bSrc = W + (size_t)brow * N + n0 + bnq;
    const uint32_t aDst = aS + (arow * ASTRIDE + akq) * 4;
    const uint32_t bDst = bS + (brow * BSTRIDE + bnq) * 4;

    float acc[2][8][4];
#pragma unroll
    for (int mt = 0; mt < 2; mt++)
#pragma unroll
        for (int nt = 0; nt < 8; nt++)
#pragma unroll
            for (int i = 0; i < 4; i++) acc[mt][nt][i] = 0.0f;

#pragma unroll
    for (int p = 0; p < 3; p++) {
        CP_ASYNC16(aDst + p * A_STAGE * 4, aSrc + p * 8);
        CP_ASYNC16(bDst + p * B_STAGE * 4, bSrc + (size_t)(p * 8) * N);
        CP_COMMIT();
    }

    for (int t = 0; t < NKT; t++) {
        CP_WAIT(2);
        __syncthreads();

        if (t + 3 < NKT) {
            const int st = (t + 3) & 3;
            CP_ASYNC16(aDst + st * A_STAGE * 4, aSrc + (t + 3) * 8);
            CP_ASYNC16(bDst + st * B_STAGE * 4, bSrc + (size_t)((t + 3) * 8) * N);
            CP_COMMIT();
        }

        const uint32_t* As = Asm + (t & 3) * A_STAGE;
        const uint32_t* Bs = Bsm + (t & 3) * B_STAGE;

        uint32_t afr[2][4];
#pragma unroll
        for (int mt = 0; mt < 2; mt++) {
            const uint32_t* ab = As + (wm + mt * 16 + r4) * ASTRIDE + c4;
            afr[mt][0] = ab[0];
            afr[mt][1] = ab[8 * ASTRIDE];
            afr[mt][2] = ab[4];
            afr[mt][3] = ab[8 * ASTRIDE + 4];
        }
#pragma unroll
        for (int nt = 0; nt < 8; nt++) {
            const int col = wn + nt * 8 + r4;
            uint32_t b0 = Bs[c4 * BSTRIDE + col];
            uint32_t b1 = Bs[(c4 + 4) * BSTRIDE + col];
            mma_tf32(acc[0][nt], afr[0][0], afr[0][1], afr[0][2], afr[0][3], b0, b1);
            mma_tf32(acc[1][nt], afr[1][0], afr[1][1], afr[1][2], afr[1][3], b0, b1);
        }
    }

#pragma unroll
    for (int mt = 0; mt < 2; mt++) {
#pragma unroll
        for (int nt = 0; nt < 8; nt++) {
            int row = m0 + wm + mt * 16 + r4;
            int col = n0 + wn + nt * 8 + 2 * c4;
            float v0 = acc[mt][nt][0], v1 = acc[mt][nt][1];
            float v2 = acc[mt][nt][2], v3 = acc[mt][nt][3];
            if (ROUND) {
                v0 = __uint_as_float(f2tf32(v0 * oscale));
                v1 = __uint_as_float(f2tf32(v1 * oscale));
                v2 = __uint_as_float(f2tf32(v2 * oscale));
                v3 = __uint_as_float(f2tf32(v3 * oscale));
            }
            float2 lo = {v0, v1};
            float2 hi = {v2, v3};
            if (HEADMAJOR) {
                int h = col >> 6, d = col & 63;
                {
                    int b = row >> 11, sq = row & 2047;
                    *(float2*)(C + (((size_t)(b * NH + h) * SEQ + sq) * HD + d)) = lo;
                }
                {
                    int r2 = row + 8;
                    int b = r2 >> 11, sq = r2 & 2047;
                    *(float2*)(C + (((size_t)(b * NH + h) * SEQ + sq) * HD + d)) = hi;
                }
            } else {
                *(float2*)(C + (size_t)row * N + col) = lo;
                *(float2*)(C + (size_t)(row + 8) * N + col) = hi;
            }
        }
    }
}

// ---------------------------------------------------------------------------
// Tensor-core flash attention (tf32 mma.sync), longest-first schedule.
// Q/K/V in g_scratch are PRE-ROUNDED tf32 bits (Q pre-scaled by 1/sqrt(HD)):
//   - K/V tiles staged via pure cp.async (no cvt, no reg staging)
//   - Q fragments reloaded per kv-tile from L1 (frees 32 regs)
// __launch_bounds__(128,4) -> 4 CTAs/SM.
// ---------------------------------------------------------------------------
__global__ __launch_bounds__(128, 4)
void flash_mma()
{
    __shared__ uint32_t Ks[64 * 76];   // K[n][d]; reused as P[row][col] stride 68
    __shared__ uint32_t Vs[64 * 76];   // V[c][d]

    const int qt  = gridDim.x - 1 - blockIdx.x;
    const int bh  = blockIdx.y;
    const int tid = threadIdx.x;
    const int warp = tid >> 5, lane = tid & 31;
    const int r4 = lane >> 2, c4 = lane & 3;
    const int wr = warp * 16;
    const int q0 = qt * 64;

    const uint32_t* Q  = (const uint32_t*)g_scratch[0] + (size_t)bh * SEQ * HD;
    const float*    Kp = g_scratch[1] + (size_t)bh * SEQ * HD;
    const float*    Vp = g_scratch[2] + (size_t)bh * SEQ * HD;

    const uint32_t* q0p = Q + (size_t)(q0 + wr + r4) * HD;
    const uint32_t* q1p = q0p + 8 * HD;

    const uint32_t ksS = (uint32_t)__cvta_generic_to_shared(Ks);
    const uint32_t vsS = (uint32_t)__cvta_generic_to_shared(Vs);
    const int cr = tid >> 4, cdv = (tid & 15) << 2;   // copy mapping

    float mA = -INFINITY, mB = -INFINITY, lA = 0.0f, lB = 0.0f;
    float o[8][4];
#pragma unroll
    for (int nt = 0; nt < 8; nt++)
#pragma unroll
        for (int i = 0; i < 4; i++) o[nt][i] = 0.0f;

    for (int kt = 0; kt <= qt; kt++) {
        const int kv0 = kt * 64;
        __syncthreads();   // prior PV reads of Ks(P)/Vs complete

        // Stage K/V tiles: pure async copies (data pre-rounded to tf32)
#pragma unroll
        for (int u = 0; u < 8; u++) {
            int r = cr + u * 8;
            CP_ASYNC16(ksS + (r * 76 + cdv) * 4, Kp + (size_t)(kv0 + r) * HD + cdv);
            CP_ASYNC16(vsS + (r * 76 + cdv) * 4, Vp + (size_t)(kv0 + r) * HD + cdv);
        }
        CP_COMMIT();
        CP_WAIT(0);
        __syncthreads();

        // S = Q @ K^T  (16x64 per warp); Q frags reloaded from L1
        float s[8][4];
#pragma unroll
        for (int nt = 0; nt < 8; nt++)
#pragma unroll
            for (int i = 0; i < 4; i++) s[nt][i] = 0.0f;

#pragma unroll
        for (int ks = 0; ks < 8; ks++) {
            const int col = ks * 8 + c4;
            uint32_t a0 = __ldg(q0p + col);
            uint32_t a1 = __ldg(q1p + col);
            uint32_t a2 = __ldg(q0p + col + 4);
            uint32_t a3 = __ldg(q1p + col + 4);
#pragma unroll
            for (int nt = 0; nt < 8; nt++) {
                uint32_t b0 = Ks[(nt * 8 + r4) * 76 + ks * 8 + c4];
                uint32_t b1 = Ks[(nt * 8 + r4) * 76 + ks * 8 + c4 + 4];
                mma_tf32(s[nt], a0, a1, a2, a3, b0, b1);
            }
        }

        if (kt == qt) {
            const int lrA = wr + r4, lrB = lrA + 8;
#pragma unroll
            for (int nt = 0; nt < 8; nt++) {
                int lc = nt * 8 + 2 * c4;
                if (lc > lrA)     s[nt][0] = -INFINITY;
                if (lc + 1 > lrA) s[nt][1] = -INFINITY;
                if (lc > lrB)     s[nt][2] = -INFINITY;
                if (lc + 1 > lrB) s[nt][3] = -INFINITY;
            }
        }

        float tmA = -INFINITY, tmB = -INFINITY;
#pragma unroll
        for (int nt = 0; nt < 8; nt++) {
            tmA = fmaxf(tmA, fmaxf(s[nt][0], s[nt][1]));
            tmB = fmaxf(tmB, fmaxf(s[nt][2], s[nt][3]));
        }
#pragma unroll
        for (int off = 1; off < 4; off <<= 1) {
            tmA = fmaxf(tmA, __shfl_xor_sync(0xffffffffu, tmA, off));
            tmB = fmaxf(tmB, __shfl_xor_sync(0xffffffffu, tmB, off));
        }
        float nmA = fmaxf(mA, tmA), nmB = fmaxf(mB, tmB);
        float scA = __expf(mA - nmA), scB = __expf(mB - nmB);
        float rsA = 0.0f, rsB = 0.0f;
#pragma unroll
        for (int nt = 0; nt < 8; nt++) {
            s[nt][0] = __expf(s[nt][0] - nmA);
            s[nt][1] = __expf(s[nt][1] - nmA);
            s[nt][2] = __expf(s[nt][2] - nmB);
            s[nt][3] = __expf(s[nt][3] - nmB);
            rsA += s[nt][0] + s[nt][1];
            rsB += s[nt][2] + s[nt][3];
        }
#pragma unroll
        for (int off = 1; off < 4; off <<= 1) {
            rsA += __shfl_xor_sync(0xffffffffu, rsA, off);
            rsB += __shfl_xor_sync(0xffffffffu, rsB, off);
        }
        lA = lA * scA + rsA;  mA = nmA;
        lB = lB * scB + rsB;  mB = nmB;
#pragma unroll
        for (int nt = 0; nt < 8; nt++) {
            o[nt][0] *= scA; o[nt][1] *= scA;
            o[nt][2] *= scB; o[nt][3] *= scB;
        }

        __syncthreads();   // all warps done reading Ks before P overwrite

        uint32_t* P = Ks;
#pragma unroll
        for (int nt = 0; nt < 8; nt++) {
            int colb = nt * 8 + 2 * c4;
            P[(wr + r4) * 68 + colb]         = f2tf32(s[nt][0]);
            P[(wr + r4) * 68 + colb + 1]     = f2tf32(s[nt][1]);
            P[(wr + r4 + 8) * 68 + colb]     = f2tf32(s[nt][2]);
            P[(wr + r4 + 8) * 68 + colb + 1] = f2tf32(s[nt][3]);
        }
        __syncwarp();

#pragma unroll
        for (int ks = 0; ks < 8; ks++) {
            uint32_t a0 = P[(wr + r4) * 68 + ks * 8 + c4];
            uint32_t a1 = P[(wr + r4 + 8) * 68 + ks * 8 + c4];
            uint32_t a2 = P[(wr + r4) * 68 + ks * 8 + c4 + 4];
            uint32_t a3 = P[(wr + r4 + 8) * 68 + ks * 8 + c4 + 4];
#pragma unroll
            for (int nt = 0; nt < 8; nt++) {
                uint32_t b0 = Vs[(ks * 8 + c4) * 76 + nt * 8 + r4];
                uint32_t b1 = Vs[(ks * 8 + c4 + 4) * 76 + nt * 8 + r4];
                mma_tf32(o[nt], a0, a1, a2, a3, b0, b1);
            }
        }
    }

    // Epilogue: O / l, tf32-rounded -> g_scratch[3] as [B, S, DIM]
    const int b = bh >> 4, h = bh & 15;
    const float invA = 1.0f / lA, invB = 1.0f / lB;
    float* Oo = g_scratch[3];
    const size_t rowA = (size_t)(b * SEQ + q0 + wr + r4) * DIM + h * HD;
    const size_t rowB = rowA + (size_t)8 * DIM;
#pragma unroll
    for (int nt = 0; nt < 8; nt++) {
        int colb = nt * 8 + 2 * c4;
        uint2 oA = {f2tf32(o[nt][0] * invA), f2tf32(o[nt][1] * invA)};
        uint2 oB = {f2tf32(o[nt][2] * invB), f2tf32(o[nt][3] * invB)};
        *(uint2*)(Oo + rowA + colb) = oA;
        *(uint2*)(Oo + rowB + colb) = oB;
    }
}

// ---------------------------------------------------------------------------
extern "C" void kernel_launch(void* const* d_in, const int* in_sizes, int n_in,
                              void* d_out, int out_size)
{
    const float* q  = (const float*)d_in[0];
    const float* k  = (const float*)d_in[1];
    const float* v  = (const float*)d_in[2];
    const float* wq = (const float*)d_in[3];
    const float* wk = (const float*)d_in[4];
    const float* wv = (const float*)d_in[5];
    const float* wo = (const float*)d_in[6];
    float* out = (float*)d_out;

    round_acts<<<dim3(MROWS * DIM / 1024, 3), 256>>>(q, k, v);
    round_wts<<<dim3(DIM * DIM / 1024, 4), 256>>>(wq, wk, wv, wo);

    dim3 ggrid(DIM / 128, MROWS / 128);   // (8, 64)

    gemm_tf32<1, 1><<<ggrid, 256>>>(0, 0, nullptr, 0, 0.125f);  // Q: scaled + rounded
    gemm_tf32<1, 1><<<ggrid, 256>>>(1, 1, nullptr, 1, 1.0f);    // K: rounded
    gemm_tf32<1, 1><<<ggrid, 256>>>(2, 2, nullptr, 2, 1.0f);    // V: rounded

    flash_mma<<<dim3(SEQ / 64, BATCH * NH), 128>>>();

    gemm_tf32<0, 0><<<ggrid, 256>>>(3, 3, out, 0, 1.0f);
}